// round 7
// baseline (speedup 1.0000x reference)
#include <cuda_runtime.h>
#include <cstdint>
#include <math.h>

// Problem constants
#define S_DIM 256
#define CH    32          // head dim
#define NH    8           // heads
#define CIN   128         // input channels
#define CQK   256         // NH*CH
#define NROWS (S_DIM * S_DIM)

typedef unsigned long long ull;

#define LOG2E 1.4426950408889634f

// ---------------------------------------------------------------------------
// Packed f32x2 helpers (sm_103a FFMA2 path — PTX-only)
// ---------------------------------------------------------------------------
__device__ __forceinline__ ull pk2(float lo, float hi) {
    ull r; asm("mov.b64 %0, {%1, %2};" : "=l"(r) : "f"(lo), "f"(hi)); return r;
}
__device__ __forceinline__ float2 upk2(ull v) {
    float lo, hi; asm("mov.b64 {%0, %1}, %2;" : "=f"(lo), "=f"(hi) : "l"(v));
    return make_float2(lo, hi);
}
__device__ __forceinline__ ull fma2(ull a, ull b, ull c) {
    ull d; asm("fma.rn.f32x2 %0, %1, %2, %3;" : "=l"(d) : "l"(a), "l"(b), "l"(c)); return d;
}
__device__ __forceinline__ ull add2(ull a, ull b) {
    ull d; asm("add.rn.f32x2 %0, %1, %2;" : "=l"(d) : "l"(a), "l"(b)); return d;
}
__device__ __forceinline__ ull mul2(ull a, ull b) {
    ull d; asm("mul.rn.f32x2 %0, %1, %2;" : "=l"(d) : "l"(a), "l"(b)); return d;
}

// ---------------------------------------------------------------------------
// FMA-pipe exp2: degree-6 Taylor + exponent stuffing (no MUFU).
// ---------------------------------------------------------------------------
__device__ __forceinline__ float fexp2(float y) {
    y = fmaxf(y, -126.0f);
    const float r  = y + 12582912.0f;
    const float nf = r - 12582912.0f;
    const float f  = y - nf;
    float p = 1.5403530393e-4f;
    p = fmaf(p, f, 1.3333355815e-3f);
    p = fmaf(p, f, 9.6181291076e-3f);
    p = fmaf(p, f, 5.5504108665e-2f);
    p = fmaf(p, f, 2.4022650696e-1f);
    p = fmaf(p, f, 6.9314718056e-1f);
    p = fmaf(p, f, 1.0f);
    const int in = (int)nf;
    return __int_as_float(__float_as_int(p) + (in << 23));
}

// ---------------------------------------------------------------------------
// Scratch
// ---------------------------------------------------------------------------
__device__ float g_Q[(size_t)NROWS * CQK];
__device__ float g_K[(size_t)NROWS * CQK];
__device__ float g_V[(size_t)NROWS * CQK];
__device__ float g_G[(size_t)NROWS * CQK];
__device__ float g_O[(size_t)NROWS * CQK];
__device__ int   g_mask_code;   // 0=int32, 1=uint8, 2=float32

// ---------------------------------------------------------------------------
// Mask dtype detection
// ---------------------------------------------------------------------------
__global__ void detect_mask_kernel(const unsigned char* __restrict__ m, int nbytes)
{
    __shared__ int f_float, f_u8;
    if (threadIdx.x == 0) { f_float = 0; f_u8 = 0; }
    __syncthreads();
    int lf = 0, lu = 0;
    for (int i = threadIdx.x; i < nbytes; i += blockDim.x) {
        unsigned char v = m[i];
        if (v >= 2) lf = 1;
        if ((i & 3) && v) lu = 1;
    }
    if (lf) atomicOr(&f_float, 1);
    if (lu) atomicOr(&f_u8, 1);
    __syncthreads();
    if (threadIdx.x == 0)
        g_mask_code = f_float ? 2 : (f_u8 ? 1 : 0);
}

// ---------------------------------------------------------------------------
// fp32 SGEMM v4: 128x128 tile, BK=8, 256 threads, 8x8 microtile via FFMA2.
// A stored in smem as PRE-DUPLICATED (a,a) 8-byte pairs -> zero pack MOVs in
// the inner loop; A-fragment = 4 broadcast LDS.128. Double-buffered.
//   mode 0: none / 1: C*=scale / 2: sigmoid(C+evec) / 3: C+evec
// ---------------------------------------------------------------------------
#define GBM 128
#define GBN 128
#define GBK 8

__global__ __launch_bounds__(256, 2)
void sgemm4(const float* __restrict__ A, const float* __restrict__ B,
            float* __restrict__ C, int M, int N, int K,
            int mode, const float* __restrict__ evec, float scale)
{
    __shared__ ull   Asd[2][GBK * GBM];   // duplicated pairs, 8KB per buffer
    __shared__ float Bs[2][GBK * GBN];    // 4KB per buffer

    const int t  = threadIdx.x;
    const int bm = blockIdx.y * GBM;
    const int bn = blockIdx.x * GBN;

    const int arow = t >> 1;
    const int ak   = (t & 1) * 4;
    const int brow = t >> 5;
    const int bcol = (t & 31) * 4;

    const int tx = t & 15;
    const int ty = t >> 4;

    ull acc2[8][4];
#pragma unroll
    for (int i = 0; i < 8; i++)
#pragma unroll
        for (int j = 0; j < 4; j++) acc2[i][j] = 0ULL;

    {
        float4 av = *(const float4*)(A + (size_t)(bm + arow) * K + ak);
        Asd[0][(ak + 0) * GBM + arow] = pk2(av.x, av.x);
        Asd[0][(ak + 1) * GBM + arow] = pk2(av.y, av.y);
        Asd[0][(ak + 2) * GBM + arow] = pk2(av.z, av.z);
        Asd[0][(ak + 3) * GBM + arow] = pk2(av.w, av.w);
        *(float4*)&Bs[0][brow * GBN + bcol] =
            *(const float4*)(B + (size_t)brow * N + bn + bcol);
    }
    __syncthreads();

    int p = 0;
    for (int k0 = 0; k0 < K; k0 += GBK) {
        const bool has_next = (k0 + GBK) < K;
        float4 av, bv;
        if (has_next) {
            av = *(const float4*)(A + (size_t)(bm + arow) * K + k0 + GBK + ak);
            bv = *(const float4*)(B + (size_t)(k0 + GBK + brow) * N + bn + bcol);
        }

        const ull*   Asp = Asd[p];
        const float* Bsp = Bs[p];
#pragma unroll
        for (int kk = 0; kk < GBK; kk++) {
            ulonglong2 aA = *(const ulonglong2*)&Asp[kk * GBM + ty * 8];
            ulonglong2 aB = *(const ulonglong2*)&Asp[kk * GBM + ty * 8 + 2];
            ulonglong2 aC = *(const ulonglong2*)&Asp[kk * GBM + ty * 8 + 4];
            ulonglong2 aD = *(const ulonglong2*)&Asp[kk * GBM + ty * 8 + 6];
            ulonglong2 b01 = *(const ulonglong2*)&Bsp[kk * GBN + tx * 8];
            ulonglong2 b23 = *(const ulonglong2*)&Bsp[kk * GBN + tx * 8 + 4];
            ull aa[8] = {aA.x, aA.y, aB.x, aB.y, aC.x, aC.y, aD.x, aD.y};
            ull b2[4] = {b01.x, b01.y, b23.x, b23.y};
#pragma unroll
            for (int i = 0; i < 8; i++)
#pragma unroll
                for (int j = 0; j < 4; j++)
                    acc2[i][j] = fma2(aa[i], b2[j], acc2[i][j]);
        }

        if (has_next) {
            const int q = p ^ 1;
            Asd[q][(ak + 0) * GBM + arow] = pk2(av.x, av.x);
            Asd[q][(ak + 1) * GBM + arow] = pk2(av.y, av.y);
            Asd[q][(ak + 2) * GBM + arow] = pk2(av.z, av.z);
            Asd[q][(ak + 3) * GBM + arow] = pk2(av.w, av.w);
            *(float4*)&Bs[q][brow * GBN + bcol] = bv;
            __syncthreads();
            p = q;
        }
    }

#pragma unroll
    for (int i = 0; i < 8; i++) {
        const int row = bm + ty * 8 + i;
        float vals[8];
#pragma unroll
        for (int j = 0; j < 4; j++) {
            float2 v = upk2(acc2[i][j]);
            vals[2 * j] = v.x; vals[2 * j + 1] = v.y;
        }
#pragma unroll
        for (int j = 0; j < 8; j++) {
            float z = vals[j];
            const int col = bn + tx * 8 + j;
            if (mode == 1)      z *= scale;
            else if (mode == 2) {
                const float y = fminf(-(z + evec[col]) * LOG2E, 126.0f);
                const float e = fexp2(y);
                z = __fdividef(1.0f, 1.0f + e);
            }
            else if (mode == 3) z += evec[col];
            vals[j] = z;
        }
        *(float4*)(C + (size_t)row * N + bn + tx * 8) =
            make_float4(vals[0], vals[1], vals[2], vals[3]);
        *(float4*)(C + (size_t)row * N + bn + tx * 8 + 4) =
            make_float4(vals[4], vals[5], vals[6], vals[7]);
    }
}

// ---------------------------------------------------------------------------
// Two-pass register-tiled attention, 512 THREADS (4 warps/SMSP for latency
// hiding). Block = (h, s, qh): 128 q rows x 256 k.
// Pass1: one 8x8 FFMA2 tile per thread (512 tiles exactly)
// Softmax: 4 threads per row (64 k each), log2-domain, poly exp2
// Pass2: 2q x 4c per thread
// ---------------------------------------------------------------------------
#define LSTR 268
#define OFF_KS   34304
#define OFF_QS   42496
#define OFF_VS   46592
#define OFF_ADDM 54784
#define OFF_RED  55040
#define OFF_RL   55552
#define ATTN_SMEM_BYTES (55680 * 4)

__global__ __launch_bounds__(512, 1)
void attn3(const float* __restrict__ Q, const float* __restrict__ Km,
           const float* __restrict__ V, const float* __restrict__ G,
           const float* __restrict__ bias, const void* __restrict__ mask,
           float* __restrict__ O)
{
    extern __shared__ float sm[];
    float* L    = sm;
    float* Ks   = sm + OFF_KS;
    float* Qs   = sm + OFF_QS;
    float* Vs   = sm + OFF_VS;
    float* addm = sm + OFF_ADDM;
    float* red  = sm + OFF_RED;
    float* rl   = sm + OFF_RL;

    const int h  = blockIdx.x;
    const int s  = blockIdx.y;
    const int qh = blockIdx.z;
    const int t  = threadIdx.x;

    // ---- stage Q transposed: Qs[c][q] (4 threads per q row, 8 c each) ----
    {
        const int q = t & 127, c0 = (t >> 7) * 8;
        const float4* src = (const float4*)(Q + ((size_t)(s * S_DIM + qh * 128 + q)) * CQK + h * CH + c0);
        float4 v0 = src[0], v1 = src[1];
        Qs[(c0 + 0) * 128 + q] = v0.x; Qs[(c0 + 1) * 128 + q] = v0.y;
        Qs[(c0 + 2) * 128 + q] = v0.z; Qs[(c0 + 3) * 128 + q] = v0.w;
        Qs[(c0 + 4) * 128 + q] = v1.x; Qs[(c0 + 5) * 128 + q] = v1.y;
        Qs[(c0 + 6) * 128 + q] = v1.z; Qs[(c0 + 7) * 128 + q] = v1.w;
    }
    // ---- stage K transposed: Ks[c][k] (2 threads per k row, 16 c each) ----
    {
        const int k = t & 255, c0 = (t >> 8) * 16;
        const float4* src = (const float4*)(Km + ((size_t)(s * S_DIM + k)) * CQK + h * CH + c0);
#pragma unroll
        for (int j = 0; j < 4; j++) {
            float4 v = src[j];
            Ks[(c0 + 4 * j + 0) * S_DIM + k] = v.x;
            Ks[(c0 + 4 * j + 1) * S_DIM + k] = v.y;
            Ks[(c0 + 4 * j + 2) * S_DIM + k] = v.z;
            Ks[(c0 + 4 * j + 3) * S_DIM + k] = v.w;
        }
    }
    // ---- stage V natural [k][c] + mask ----
    {
        const float4* Vg4 = (const float4*)V;
        const size_t rowbase = ((size_t)s * S_DIM) * (CQK / 4) + h * (CH / 4);
#pragma unroll
        for (int f = t; f < S_DIM * (CH / 4); f += 512) {
            int k = f >> 3, c4 = f & 7;
            ((float4*)Vs)[k * 8 + c4] = Vg4[rowbase + (size_t)k * (CQK / 4) + c4];
        }
        if (t < 256) {
            const int idx = s * S_DIM + t;
            const int code = g_mask_code;
            bool mv;
            if (code == 2)      mv = ((const float*)mask)[idx] != 0.f;
            else if (code == 1) mv = ((const unsigned char*)mask)[idx] != 0;
            else                mv = ((const int*)mask)[idx] != 0;
            addm[t] = mv ? 0.f : -1e30f;
        }
    }
    __syncthreads();

    // ---- pass 1: QK^T, one 8x8 tile per thread; L in log2 domain ----
    const float* brow = bias + ((size_t)(h * S_DIM + qh * 128)) * S_DIM;
    {
        const int qi = t >> 5, ki = t & 31;    // qi uniform within a warp
        const int q0 = qi * 8, k0 = ki * 8;

        ull acc2[8][4];
#pragma unroll
        for (int i = 0; i < 8; i++)
#pragma unroll
            for (int j = 0; j < 4; j++) acc2[i][j] = 0ULL;

#pragma unroll 2
        for (int c = 0; c < CH; c++) {
            float4 qa = *(const float4*)&Qs[c * 128 + q0];
            float4 qb = *(const float4*)&Qs[c * 128 + q0 + 4];
            ulonglong2 kA = *(const ulonglong2*)&Ks[c * S_DIM + k0];
            ulonglong2 kB = *(const ulonglong2*)&Ks[c * S_DIM + k0 + 4];
            ull b2[4] = {kA.x, kA.y, kB.x, kB.y};
            ull aa[8] = {pk2(qa.x, qa.x), pk2(qa.y, qa.y), pk2(qa.z, qa.z), pk2(qa.w, qa.w),
                         pk2(qb.x, qb.x), pk2(qb.y, qb.y), pk2(qb.z, qb.z), pk2(qb.w, qb.w)};
#pragma unroll
            for (int i = 0; i < 8; i++)
#pragma unroll
                for (int j = 0; j < 4; j++)
                    acc2[i][j] = fma2(aa[i], b2[j], acc2[i][j]);
        }
        float4 am0 = *(const float4*)&addm[k0];
        float4 am1 = *(const float4*)&addm[k0 + 4];
#pragma unroll
        for (int i = 0; i < 8; i++) {
            const int q = q0 + i;
            float4 bb0 = *(const float4*)(brow + (size_t)q * S_DIM + k0);
            float4 bb1 = *(const float4*)(brow + (size_t)q * S_DIM + k0 + 4);
            float2 d0 = upk2(acc2[i][0]);
            float2 d1 = upk2(acc2[i][1]);
            float2 d2 = upk2(acc2[i][2]);
            float2 d3 = upk2(acc2[i][3]);
            *(float4*)&L[q * LSTR + k0] = make_float4(
                (d0.x + bb0.x + am0.x) * LOG2E, (d0.y + bb0.y + am0.y) * LOG2E,
                (d1.x + bb0.z + am0.z) * LOG2E, (d1.y + bb0.w + am0.w) * LOG2E);
            *(float4*)&L[q * LSTR + k0 + 4] = make_float4(
                (d2.x + bb1.x + am1.x) * LOG2E, (d2.y + bb1.y + am1.y) * LOG2E,
                (d3.x + bb1.z + am1.z) * LOG2E, (d3.y + bb1.w + am1.w) * LOG2E);
        }
    }
    __syncthreads();

    // ---- softmax: 4 threads per row, 64 k each ----
    {
        const int row = t >> 2, qtr = t & 3;
        float* lr = &L[row * LSTR + qtr * 64];
        float mx = -INFINITY;
#pragma unroll 4
        for (int j = 0; j < 16; j++) {
            float4 v = ((const float4*)lr)[j];
            mx = fmaxf(mx, fmaxf(fmaxf(v.x, v.y), fmaxf(v.z, v.w)));
        }
        red[row * 4 + qtr] = mx;
        __syncthreads();
        const float mrow = fmaxf(fmaxf(red[row * 4], red[row * 4 + 1]),
                                 fmaxf(red[row * 4 + 2], red[row * 4 + 3]));
        float ss = 0.f;
#pragma unroll 4
        for (int j = 0; j < 16; j++) {
            float4 v = ((const float4*)lr)[j];
            v.x = fexp2(v.x - mrow); v.y = fexp2(v.y - mrow);
            v.z = fexp2(v.z - mrow); v.w = fexp2(v.w - mrow);
            ss += (v.x + v.y) + (v.z + v.w);
            ((float4*)lr)[j] = v;
        }
        __syncthreads();
        red[row * 4 + qtr] = ss;
        __syncthreads();
        if (qtr == 0)
            rl[row] = 1.f / (red[row * 4] + red[row * 4 + 1] +
                             red[row * 4 + 2] + red[row * 4 + 3]);
    }
    __syncthreads();

    // ---- pass 2: O = P.V, 2q x 4c per thread ----
    {
        const int q0 = (t >> 3) * 2;
        const int c0 = (t & 7) * 4;
        ull acc2[2][2];
        acc2[0][0] = acc2[0][1] = acc2[1][0] = acc2[1][1] = 0ULL;

#pragma unroll 4
        for (int k0 = 0; k0 < S_DIM; k0 += 4) {
            ulonglong2 v0 = *(const ulonglong2*)&Vs[(k0 + 0) * CH + c0];
            ulonglong2 v1 = *(const ulonglong2*)&Vs[(k0 + 1) * CH + c0];
            ulonglong2 v2 = *(const ulonglong2*)&Vs[(k0 + 2) * CH + c0];
            ulonglong2 v3 = *(const ulonglong2*)&Vs[(k0 + 3) * CH + c0];
#pragma unroll
            for (int i = 0; i < 2; i++) {
                float4 pv = *(const float4*)&L[(q0 + i) * LSTR + k0];
                ull a0 = pk2(pv.x, pv.x);
                ull a1 = pk2(pv.y, pv.y);
                ull a2 = pk2(pv.z, pv.z);
                ull a3 = pk2(pv.w, pv.w);
                acc2[i][0] = fma2(a0, v0.x, acc2[i][0]);
                acc2[i][1] = fma2(a0, v0.y, acc2[i][1]);
                acc2[i][0] = fma2(a1, v1.x, acc2[i][0]);
                acc2[i][1] = fma2(a1, v1.y, acc2[i][1]);
                acc2[i][0] = fma2(a2, v2.x, acc2[i][0]);
                acc2[i][1] = fma2(a2, v2.y, acc2[i][1]);
                acc2[i][0] = fma2(a3, v3.x, acc2[i][0]);
                acc2[i][1] = fma2(a3, v3.y, acc2[i][1]);
            }
        }
#pragma unroll
        for (int i = 0; i < 2; i++) {
            const int q = q0 + i;
            const float rv = rl[q];
            const size_t row = (size_t)(s * S_DIM + qh * 128 + q);
            float4 gv = *(const float4*)(G + row * CQK + h * CH + c0);
            float2 x0 = upk2(acc2[i][0]);
            float2 x1 = upk2(acc2[i][1]);
            float4 ov;
            ov.x = x0.x * rv * gv.x;
            ov.y = x0.y * rv * gv.y;
            ov.z = x1.x * rv * gv.z;
            ov.w = x1.y * rv * gv.w;
            *(float4*)(O + row * CQK + h * CH + c0) = ov;
        }
    }
}

// ---------------------------------------------------------------------------
// Launch
// ---------------------------------------------------------------------------
extern "C" void kernel_launch(void* const* d_in, const int* in_sizes, int n_in,
                              void* d_out, int out_size)
{
    const float* x    = (const float*)d_in[0];
    const float* bias = (const float*)d_in[1];
    const void*  mask = d_in[2];
    const float* Wq   = (const float*)d_in[3];
    const float* Wk   = (const float*)d_in[4];
    const float* Wv   = (const float*)d_in[5];
    const float* Wo   = (const float*)d_in[6];
    const float* bo   = (const float*)d_in[7];
    const float* Wg   = (const float*)d_in[8];
    const float* bg   = (const float*)d_in[9];
    float* out = (float*)d_out;

    void *pQ, *pK, *pV, *pG, *pO;
    cudaGetSymbolAddress(&pQ, g_Q);
    cudaGetSymbolAddress(&pK, g_K);
    cudaGetSymbolAddress(&pV, g_V);
    cudaGetSymbolAddress(&pG, g_G);
    cudaGetSymbolAddress(&pO, g_O);
    float* Qb = (float*)pQ; float* Kb = (float*)pK; float* Vb = (float*)pV;
    float* Gb = (float*)pG; float* Ob = (float*)pO;

    const float qscale = 0.17677669529663687f;   // 1/sqrt(32)

    dim3 gproj(CQK / GBN, NROWS / GBM);   // (2, 512)
    sgemm4<<<gproj, 256>>>(x, Wq, Qb, NROWS, CQK, CIN, 1, nullptr, qscale);
    sgemm4<<<gproj, 256>>>(x, Wk, Kb, NROWS, CQK, CIN, 0, nullptr, 1.f);
    sgemm4<<<gproj, 256>>>(x, Wv, Vb, NROWS, CQK, CIN, 0, nullptr, 1.f);
    sgemm4<<<gproj, 256>>>(x, Wg, Gb, NROWS, CQK, CIN, 2, bg, 1.f);

    detect_mask_kernel<<<1, 256>>>((const unsigned char*)mask, S_DIM * S_DIM);

    cudaFuncSetAttribute(attn3, cudaFuncAttributeMaxDynamicSharedMemorySize, ATTN_SMEM_BYTES);
    attn3<<<dim3(NH, S_DIM, 2), 512, ATTN_SMEM_BYTES>>>(Qb, Kb, Vb, Gb, bias, mask, Ob);

    dim3 gout(CIN / GBN, NROWS / GBM);    // (1, 512)
    sgemm4<<<gout, 256>>>(Ob, Wo, out, NROWS, CIN, CQK, 3, bo, 1.f);
}

// round 8
// speedup vs baseline: 1.3360x; 1.3360x over previous
#include <cuda_runtime.h>
#include <cstdint>
#include <math.h>

// Problem constants
#define S_DIM 256
#define CH    32          // head dim
#define NH    8           // heads
#define CIN   128         // input channels
#define CQK   256         // NH*CH
#define NROWS (S_DIM * S_DIM)

typedef unsigned long long ull;

// ---------------------------------------------------------------------------
// Packed f32x2 helpers (sm_103a FFMA2 path — PTX-only)
// ---------------------------------------------------------------------------
__device__ __forceinline__ ull pk2(float lo, float hi) {
    ull r; asm("mov.b64 %0, {%1, %2};" : "=l"(r) : "f"(lo), "f"(hi)); return r;
}
__device__ __forceinline__ float2 upk2(ull v) {
    float lo, hi; asm("mov.b64 {%0, %1}, %2;" : "=f"(lo), "=f"(hi) : "l"(v));
    return make_float2(lo, hi);
}
__device__ __forceinline__ ull fma2(ull a, ull b, ull c) {
    ull d; asm("fma.rn.f32x2 %0, %1, %2, %3;" : "=l"(d) : "l"(a), "l"(b), "l"(c)); return d;
}
__device__ __forceinline__ ull add2(ull a, ull b) {
    ull d; asm("add.rn.f32x2 %0, %1, %2;" : "=l"(d) : "l"(a), "l"(b)); return d;
}
__device__ __forceinline__ ull mul2(ull a, ull b) {
    ull d; asm("mul.rn.f32x2 %0, %1, %2;" : "=l"(d) : "l"(a), "l"(b)); return d;
}

// ---------------------------------------------------------------------------
// Scratch
// ---------------------------------------------------------------------------
__device__ float g_Q[(size_t)NROWS * CQK];
__device__ float g_K[(size_t)NROWS * CQK];
__device__ float g_V[(size_t)NROWS * CQK];
__device__ float g_G[(size_t)NROWS * CQK];
__device__ float g_O[(size_t)NROWS * CQK];
__device__ int   g_mask_code;   // 0=int32, 1=uint8, 2=float32

// ---------------------------------------------------------------------------
// Mask dtype detection
// ---------------------------------------------------------------------------
__global__ void detect_mask_kernel(const unsigned char* __restrict__ m, int nbytes)
{
    __shared__ int f_float, f_u8;
    if (threadIdx.x == 0) { f_float = 0; f_u8 = 0; }
    __syncthreads();
    int lf = 0, lu = 0;
    for (int i = threadIdx.x; i < nbytes; i += blockDim.x) {
        unsigned char v = m[i];
        if (v >= 2) lf = 1;
        if ((i & 3) && v) lu = 1;
    }
    if (lf) atomicOr(&f_float, 1);
    if (lu) atomicOr(&f_u8, 1);
    __syncthreads();
    if (threadIdx.x == 0)
        g_mask_code = f_float ? 2 : (f_u8 ? 1 : 0);
}

// ---------------------------------------------------------------------------
// fp32 SGEMM v5: 128x128 tile, BK=8, 256 threads, FFMA2 microtile organized
// as 2x2 blocks of 4x4 so every B-fragment LDS.128 is 8 lanes x contiguous
// 16B (bank-conflict-free). Rows: {ty*4..+3} u {64+ty*4..+3};
// cols: {tx*4..+3} u {64+tx*4..+3}. Double-buffered smem.
//   mode 0: none / 1: C*=scale / 2: sigmoid(C+evec) / 3: C+evec
// ---------------------------------------------------------------------------
#define GBM 128
#define GBN 128
#define GBK 8

__global__ __launch_bounds__(256, 2)
void sgemm5(const float* __restrict__ A, const float* __restrict__ B,
            float* __restrict__ C, int M, int N, int K,
            int mode, const float* __restrict__ evec, float scale)
{
    __shared__ float As[2][GBK * GBM];   // [k][m]
    __shared__ float Bs[2][GBK * GBN];   // [k][n]

    const int t  = threadIdx.x;
    const int bm = blockIdx.y * GBM;
    const int bn = blockIdx.x * GBN;

    const int arow = t >> 1;
    const int ak   = (t & 1) * 4;
    const int brow = t >> 5;
    const int bcol = (t & 31) * 4;

    const int tx = t & 15;
    const int ty = t >> 4;

    ull acc2[8][4];
#pragma unroll
    for (int i = 0; i < 8; i++)
#pragma unroll
        for (int j = 0; j < 4; j++) acc2[i][j] = 0ULL;

    {
        float4 av = *(const float4*)(A + (size_t)(bm + arow) * K + ak);
        As[0][(ak + 0) * GBM + arow] = av.x;
        As[0][(ak + 1) * GBM + arow] = av.y;
        As[0][(ak + 2) * GBM + arow] = av.z;
        As[0][(ak + 3) * GBM + arow] = av.w;
        *(float4*)&Bs[0][brow * GBN + bcol] =
            *(const float4*)(B + (size_t)brow * N + bn + bcol);
    }
    __syncthreads();

    int p = 0;
    for (int k0 = 0; k0 < K; k0 += GBK) {
        const bool has_next = (k0 + GBK) < K;
        float4 av, bv;
        if (has_next) {
            av = *(const float4*)(A + (size_t)(bm + arow) * K + k0 + GBK + ak);
            bv = *(const float4*)(B + (size_t)(k0 + GBK + brow) * N + bn + bcol);
        }

        const float* Asp = As[p];
        const float* Bsp = Bs[p];
#pragma unroll
        for (int kk = 0; kk < GBK; kk++) {
            float4 a0 = *(const float4*)&Asp[kk * GBM + ty * 4];        // broadcast
            float4 a1 = *(const float4*)&Asp[kk * GBM + 64 + ty * 4];   // broadcast
            ulonglong2 b0 = *(const ulonglong2*)&Bsp[kk * GBN + tx * 4];      // CF
            ulonglong2 b1 = *(const ulonglong2*)&Bsp[kk * GBN + 64 + tx * 4]; // CF
            ull b2[4] = {b0.x, b0.y, b1.x, b1.y};
            ull aa[8] = {pk2(a0.x, a0.x), pk2(a0.y, a0.y), pk2(a0.z, a0.z), pk2(a0.w, a0.w),
                         pk2(a1.x, a1.x), pk2(a1.y, a1.y), pk2(a1.z, a1.z), pk2(a1.w, a1.w)};
#pragma unroll
            for (int i = 0; i < 8; i++)
#pragma unroll
                for (int j = 0; j < 4; j++)
                    acc2[i][j] = fma2(aa[i], b2[j], acc2[i][j]);
        }

        if (has_next) {
            const int q = p ^ 1;
            As[q][(ak + 0) * GBM + arow] = av.x;
            As[q][(ak + 1) * GBM + arow] = av.y;
            As[q][(ak + 2) * GBM + arow] = av.z;
            As[q][(ak + 3) * GBM + arow] = av.w;
            *(float4*)&Bs[q][brow * GBN + bcol] = bv;
            __syncthreads();
            p = q;
        }
    }

#pragma unroll
    for (int i = 0; i < 8; i++) {
        const int row = bm + ((i < 4) ? (ty * 4 + i) : (64 + ty * 4 + i - 4));
        float vlo[4], vhi[4];
        {
            float2 v0 = upk2(acc2[i][0]);
            float2 v1 = upk2(acc2[i][1]);
            vlo[0] = v0.x; vlo[1] = v0.y; vlo[2] = v1.x; vlo[3] = v1.y;
            float2 v2 = upk2(acc2[i][2]);
            float2 v3 = upk2(acc2[i][3]);
            vhi[0] = v2.x; vhi[1] = v2.y; vhi[2] = v3.x; vhi[3] = v3.y;
        }
#pragma unroll
        for (int j = 0; j < 4; j++) {
            const int clo = bn + tx * 4 + j;
            const int chi = bn + 64 + tx * 4 + j;
            float zl = vlo[j], zh = vhi[j];
            if (mode == 1)      { zl *= scale; zh *= scale; }
            else if (mode == 2) {
                zl = 1.f / (1.f + __expf(-(zl + evec[clo])));
                zh = 1.f / (1.f + __expf(-(zh + evec[chi])));
            }
            else if (mode == 3) { zl += evec[clo]; zh += evec[chi]; }
            vlo[j] = zl; vhi[j] = zh;
        }
        *(float4*)(C + (size_t)row * N + bn + tx * 4) =
            make_float4(vlo[0], vlo[1], vlo[2], vlo[3]);
        *(float4*)(C + (size_t)row * N + bn + 64 + tx * 4) =
            make_float4(vhi[0], vhi[1], vhi[2], vhi[3]);
    }
}

// ---------------------------------------------------------------------------
// Two-pass register-tiled attention, 256 threads, conflict-free pass-1.
// Block = (h, s, qh): 128 q rows x 256 k.
// Pass1: 8x8 FFMA2 microtile per (tile), 2 tiles/thread; a thread's k columns
//        are {ki*4..+3} u {128+ki*4..+3} -> all Ks loads conflict-free.
// Softmax: 2 threads/row, __expf.
// Pass2: 4q x 4c per thread (broadcast P, conflict-free V).
// ---------------------------------------------------------------------------
#define LSTR 268
#define OFF_KS   34304
#define OFF_QS   42496
#define OFF_VS   46592
#define OFF_ADDM 54784
#define OFF_RED  55040
#define OFF_RL   55296
#define ATTN_SMEM_BYTES (55424 * 4)

__global__ __launch_bounds__(256, 1)
void attn4(const float* __restrict__ Q, const float* __restrict__ Km,
           const float* __restrict__ V, const float* __restrict__ G,
           const float* __restrict__ bias, const void* __restrict__ mask,
           float* __restrict__ O)
{
    extern __shared__ float sm[];
    float* L    = sm;
    float* Ks   = sm + OFF_KS;
    float* Qs   = sm + OFF_QS;
    float* Vs   = sm + OFF_VS;
    float* addm = sm + OFF_ADDM;
    float* red  = sm + OFF_RED;
    float* rl   = sm + OFF_RL;

    const int h  = blockIdx.x;
    const int s  = blockIdx.y;
    const int qh = blockIdx.z;
    const int t  = threadIdx.x;

    // ---- stage Q transposed: Qs[c][q] ----
    {
        const int q = t >> 1, c0 = (t & 1) * 16;
        const float4* src = (const float4*)(Q + ((size_t)(s * S_DIM + qh * 128 + q)) * CQK + h * CH + c0);
#pragma unroll
        for (int j = 0; j < 4; j++) {
            float4 v = src[j];
            Qs[(c0 + 4 * j + 0) * 128 + q] = v.x;
            Qs[(c0 + 4 * j + 1) * 128 + q] = v.y;
            Qs[(c0 + 4 * j + 2) * 128 + q] = v.z;
            Qs[(c0 + 4 * j + 3) * 128 + q] = v.w;
        }
    }
    // ---- stage K transposed: Ks[c][k] ----
    {
        const int k = t;
        const float4* src = (const float4*)(Km + ((size_t)(s * S_DIM + k)) * CQK + h * CH);
#pragma unroll
        for (int j = 0; j < 8; j++) {
            float4 v = src[j];
            Ks[(4 * j + 0) * S_DIM + k] = v.x;
            Ks[(4 * j + 1) * S_DIM + k] = v.y;
            Ks[(4 * j + 2) * S_DIM + k] = v.z;
            Ks[(4 * j + 3) * S_DIM + k] = v.w;
        }
    }
    // ---- stage V natural [k][c] + mask ----
    {
        const float4* Vg4 = (const float4*)V;
        const size_t rowbase = ((size_t)s * S_DIM) * (CQK / 4) + h * (CH / 4);
#pragma unroll
        for (int f = t; f < S_DIM * (CH / 4); f += 256) {
            int k = f >> 3, c4 = f & 7;
            ((float4*)Vs)[k * 8 + c4] = Vg4[rowbase + (size_t)k * (CQK / 4) + c4];
        }
        const int idx = s * S_DIM + t;
        const int code = g_mask_code;
        bool mv;
        if (code == 2)      mv = ((const float*)mask)[idx] != 0.f;
        else if (code == 1) mv = ((const unsigned char*)mask)[idx] != 0;
        else                mv = ((const int*)mask)[idx] != 0;
        addm[t] = mv ? 0.f : -1e30f;
    }
    __syncthreads();

    // ---- pass 1: QK^T, split k-groups, 2 tiles/thread ----
    const float* brow = bias + ((size_t)(h * S_DIM + qh * 128)) * S_DIM;
#pragma unroll
    for (int rep = 0; rep < 2; rep++) {
        const int tile = t + rep * 256;
        const int qi = tile >> 5, ki = tile & 31;   // qi warp-uniform
        const int q0 = qi * 8;
        const int kA = ki * 4, kB = 128 + ki * 4;

        ull acc2[8][4];
#pragma unroll
        for (int i = 0; i < 8; i++)
#pragma unroll
            for (int j = 0; j < 4; j++) acc2[i][j] = 0ULL;

#pragma unroll 2
        for (int c = 0; c < CH; c++) {
            float4 qa = *(const float4*)&Qs[c * 128 + q0];        // broadcast
            float4 qb = *(const float4*)&Qs[c * 128 + q0 + 4];    // broadcast
            ulonglong2 k0v = *(const ulonglong2*)&Ks[c * S_DIM + kA];  // CF
            ulonglong2 k1v = *(const ulonglong2*)&Ks[c * S_DIM + kB];  // CF
            ull b2[4] = {k0v.x, k0v.y, k1v.x, k1v.y};
            ull aa[8] = {pk2(qa.x, qa.x), pk2(qa.y, qa.y), pk2(qa.z, qa.z), pk2(qa.w, qa.w),
                         pk2(qb.x, qb.x), pk2(qb.y, qb.y), pk2(qb.z, qb.z), pk2(qb.w, qb.w)};
#pragma unroll
            for (int i = 0; i < 8; i++)
#pragma unroll
                for (int j = 0; j < 4; j++)
                    acc2[i][j] = fma2(aa[i], b2[j], acc2[i][j]);
        }
        // epilogue: + bias + mask -> L (two conflict-free float4 stores/row)
        float4 amA = *(const float4*)&addm[kA];
        float4 amB = *(const float4*)&addm[kB];
#pragma unroll
        for (int i = 0; i < 8; i++) {
            const int q = q0 + i;
            float4 bbA = *(const float4*)(brow + (size_t)q * S_DIM + kA);
            float4 bbB = *(const float4*)(brow + (size_t)q * S_DIM + kB);
            float2 d0 = upk2(acc2[i][0]);
            float2 d1 = upk2(acc2[i][1]);
            float2 d2 = upk2(acc2[i][2]);
            float2 d3 = upk2(acc2[i][3]);
            *(float4*)&L[q * LSTR + kA] =
                make_float4(d0.x + bbA.x + amA.x, d0.y + bbA.y + amA.y,
                            d1.x + bbA.z + amA.z, d1.y + bbA.w + amA.w);
            *(float4*)&L[q * LSTR + kB] =
                make_float4(d2.x + bbB.x + amB.x, d2.y + bbB.y + amB.y,
                            d3.x + bbB.z + amB.z, d3.y + bbB.w + amB.w);
        }
    }
    __syncthreads();

    // ---- softmax: 2 threads per row, 128 k each ----
    {
        const int row = t >> 1, half = t & 1;
        float* lr = &L[row * LSTR + half * 128];
        float mx = -INFINITY;
#pragma unroll 4
        for (int j = 0; j < 32; j++) {
            float4 v = ((const float4*)lr)[j];
            mx = fmaxf(mx, fmaxf(fmaxf(v.x, v.y), fmaxf(v.z, v.w)));
        }
        red[row * 2 + half] = mx;
        __syncthreads();
        const float mrow = fmaxf(red[row * 2], red[row * 2 + 1]);
        float ss = 0.f;
#pragma unroll 4
        for (int j = 0; j < 32; j++) {
            float4 v = ((const float4*)lr)[j];
            v.x = __expf(v.x - mrow); v.y = __expf(v.y - mrow);
            v.z = __expf(v.z - mrow); v.w = __expf(v.w - mrow);
            ss += (v.x + v.y) + (v.z + v.w);
            ((float4*)lr)[j] = v;
        }
        __syncthreads();
        red[row * 2 + half] = ss;
        __syncthreads();
        if (half == 0) rl[row] = 1.f / (red[row * 2] + red[row * 2 + 1]);
    }
    __syncthreads();

    // ---- pass 2: O = P.V, 4q x 4c per thread ----
    {
        const int qi = t >> 3, ci = t & 7;
        const int q0 = qi * 4, c0 = ci * 4;
        ull acc2[4][2];
#pragma unroll
        for (int i = 0; i < 4; i++) { acc2[i][0] = 0ULL; acc2[i][1] = 0ULL; }

#pragma unroll 2
        for (int k0 = 0; k0 < S_DIM; k0 += 4) {
            ulonglong2 v0 = *(const ulonglong2*)&Vs[(k0 + 0) * CH + c0];
            ulonglong2 v1 = *(const ulonglong2*)&Vs[(k0 + 1) * CH + c0];
            ulonglong2 v2 = *(const ulonglong2*)&Vs[(k0 + 2) * CH + c0];
            ulonglong2 v3 = *(const ulonglong2*)&Vs[(k0 + 3) * CH + c0];
#pragma unroll
            for (int i = 0; i < 4; i++) {
                float4 pv = *(const float4*)&L[(q0 + i) * LSTR + k0];
                ull a0 = pk2(pv.x, pv.x);
                ull a1 = pk2(pv.y, pv.y);
                ull a2 = pk2(pv.z, pv.z);
                ull a3 = pk2(pv.w, pv.w);
                acc2[i][0] = fma2(a0, v0.x, acc2[i][0]);
                acc2[i][1] = fma2(a0, v0.y, acc2[i][1]);
                acc2[i][0] = fma2(a1, v1.x, acc2[i][0]);
                acc2[i][1] = fma2(a1, v1.y, acc2[i][1]);
                acc2[i][0] = fma2(a2, v2.x, acc2[i][0]);
                acc2[i][1] = fma2(a2, v2.y, acc2[i][1]);
                acc2[i][0] = fma2(a3, v3.x, acc2[i][0]);
                acc2[i][1] = fma2(a3, v3.y, acc2[i][1]);
            }
        }
#pragma unroll
        for (int i = 0; i < 4; i++) {
            const int q = q0 + i;
            const float rv = rl[q];
            const size_t row = (size_t)(s * S_DIM + qh * 128 + q);
            float4 gv = *(const float4*)(G + row * CQK + h * CH + c0);
            float2 x0 = upk2(acc2[i][0]);
            float2 x1 = upk2(acc2[i][1]);
            float4 ov;
            ov.x = x0.x * rv * gv.x;
            ov.y = x0.y * rv * gv.y;
            ov.z = x1.x * rv * gv.z;
            ov.w = x1.y * rv * gv.w;
            *(float4*)(O + row * CQK + h * CH + c0) = ov;
        }
    }
}

// ---------------------------------------------------------------------------
// Launch
// ---------------------------------------------------------------------------
extern "C" void kernel_launch(void* const* d_in, const int* in_sizes, int n_in,
                              void* d_out, int out_size)
{
    const float* x    = (const float*)d_in[0];
    const float* bias = (const float*)d_in[1];
    const void*  mask = d_in[2];
    const float* Wq   = (const float*)d_in[3];
    const float* Wk   = (const float*)d_in[4];
    const float* Wv   = (const float*)d_in[5];
    const float* Wo   = (const float*)d_in[6];
    const float* bo   = (const float*)d_in[7];
    const float* Wg   = (const float*)d_in[8];
    const float* bg   = (const float*)d_in[9];
    float* out = (float*)d_out;

    void *pQ, *pK, *pV, *pG, *pO;
    cudaGetSymbolAddress(&pQ, g_Q);
    cudaGetSymbolAddress(&pK, g_K);
    cudaGetSymbolAddress(&pV, g_V);
    cudaGetSymbolAddress(&pG, g_G);
    cudaGetSymbolAddress(&pO, g_O);
    float* Qb = (float*)pQ; float* Kb = (float*)pK; float* Vb = (float*)pV;
    float* Gb = (float*)pG; float* Ob = (float*)pO;

    const float qscale = 0.17677669529663687f;   // 1/sqrt(32)

    dim3 gproj(CQK / GBN, NROWS / GBM);   // (2, 512)
    sgemm5<<<gproj, 256>>>(x, Wq, Qb, NROWS, CQK, CIN, 1, nullptr, qscale);
    sgemm5<<<gproj, 256>>>(x, Wk, Kb, NROWS, CQK, CIN, 0, nullptr, 1.f);
    sgemm5<<<gproj, 256>>>(x, Wv, Vb, NROWS, CQK, CIN, 0, nullptr, 1.f);
    sgemm5<<<gproj, 256>>>(x, Wg, Gb, NROWS, CQK, CIN, 2, bg, 1.f);

    detect_mask_kernel<<<1, 256>>>((const unsigned char*)mask, S_DIM * S_DIM);

    cudaFuncSetAttribute(attn4, cudaFuncAttributeMaxDynamicSharedMemorySize, ATTN_SMEM_BYTES);
    attn4<<<dim3(NH, S_DIM, 2), 256, ATTN_SMEM_BYTES>>>(Qb, Kb, Vb, Gb, bias, mask, Ob);

    dim3 gout(CIN / GBN, NROWS / GBM);    // (1, 512)
    sgemm5<<<gout, 256>>>(Ob, Wo, out, NROWS, CIN, CQK, 3, bo, 1.f);
}

// round 9
// speedup vs baseline: 1.3693x; 1.0249x over previous
#include <cuda_runtime.h>
#include <cstdint>
#include <math.h>

// Problem constants
#define S_DIM 256
#define CH    32          // head dim
#define NH    8           // heads
#define CIN   128         // input channels
#define CQK   256         // NH*CH
#define NROWS (S_DIM * S_DIM)

typedef unsigned long long ull;

// ---------------------------------------------------------------------------
// Packed f32x2 helpers (sm_103a FFMA2 path — PTX-only)
// ---------------------------------------------------------------------------
__device__ __forceinline__ ull pk2(float lo, float hi) {
    ull r; asm("mov.b64 %0, {%1, %2};" : "=l"(r) : "f"(lo), "f"(hi)); return r;
}
__device__ __forceinline__ float2 upk2(ull v) {
    float lo, hi; asm("mov.b64 {%0, %1}, %2;" : "=f"(lo), "=f"(hi) : "l"(v));
    return make_float2(lo, hi);
}
__device__ __forceinline__ ull fma2(ull a, ull b, ull c) {
    ull d; asm("fma.rn.f32x2 %0, %1, %2, %3;" : "=l"(d) : "l"(a), "l"(b), "l"(c)); return d;
}
__device__ __forceinline__ ull add2(ull a, ull b) {
    ull d; asm("add.rn.f32x2 %0, %1, %2;" : "=l"(d) : "l"(a), "l"(b)); return d;
}
__device__ __forceinline__ ull mul2(ull a, ull b) {
    ull d; asm("mul.rn.f32x2 %0, %1, %2;" : "=l"(d) : "l"(a), "l"(b)); return d;
}

// ---------------------------------------------------------------------------
// Scratch
// ---------------------------------------------------------------------------
__device__ float g_Q[(size_t)NROWS * CQK];
__device__ float g_K[(size_t)NROWS * CQK];
__device__ float g_V[(size_t)NROWS * CQK];
__device__ float g_G[(size_t)NROWS * CQK];
__device__ float g_O[(size_t)NROWS * CQK];
__device__ int   g_mask_code;   // 0=int32, 1=uint8, 2=float32

// ---------------------------------------------------------------------------
// Mask dtype detection
// ---------------------------------------------------------------------------
__global__ void detect_mask_kernel(const unsigned char* __restrict__ m, int nbytes)
{
    __shared__ int f_float, f_u8;
    if (threadIdx.x == 0) { f_float = 0; f_u8 = 0; }
    __syncthreads();
    int lf = 0, lu = 0;
    for (int i = threadIdx.x; i < nbytes; i += blockDim.x) {
        unsigned char v = m[i];
        if (v >= 2) lf = 1;
        if ((i & 3) && v) lu = 1;
    }
    if (lf) atomicOr(&f_float, 1);
    if (lu) atomicOr(&f_u8, 1);
    __syncthreads();
    if (threadIdx.x == 0)
        g_mask_code = f_float ? 2 : (f_u8 ? 1 : 0);
}

// ---------------------------------------------------------------------------
// fp32 SGEMM v5 (unchanged, passing at 96.6us): 128x128 tile, BK=8,
// 256 threads, FFMA2 microtile as 2x2 blocks of 4x4 (conflict-free B loads).
//   mode 0: none / 1: C*=scale / 2: sigmoid(C+evec) / 3: C+evec
// ---------------------------------------------------------------------------
#define GBM 128
#define GBN 128
#define GBK 8

__global__ __launch_bounds__(256, 2)
void sgemm5(const float* __restrict__ A, const float* __restrict__ B,
            float* __restrict__ C, int M, int N, int K,
            int mode, const float* __restrict__ evec, float scale)
{
    __shared__ float As[2][GBK * GBM];   // [k][m]
    __shared__ float Bs[2][GBK * GBN];   // [k][n]

    const int t  = threadIdx.x;
    const int bm = blockIdx.y * GBM;
    const int bn = blockIdx.x * GBN;

    const int arow = t >> 1;
    const int ak   = (t & 1) * 4;
    const int brow = t >> 5;
    const int bcol = (t & 31) * 4;

    const int tx = t & 15;
    const int ty = t >> 4;

    ull acc2[8][4];
#pragma unroll
    for (int i = 0; i < 8; i++)
#pragma unroll
        for (int j = 0; j < 4; j++) acc2[i][j] = 0ULL;

    {
        float4 av = *(const float4*)(A + (size_t)(bm + arow) * K + ak);
        As[0][(ak + 0) * GBM + arow] = av.x;
        As[0][(ak + 1) * GBM + arow] = av.y;
        As[0][(ak + 2) * GBM + arow] = av.z;
        As[0][(ak + 3) * GBM + arow] = av.w;
        *(float4*)&Bs[0][brow * GBN + bcol] =
            *(const float4*)(B + (size_t)brow * N + bn + bcol);
    }
    __syncthreads();

    int p = 0;
    for (int k0 = 0; k0 < K; k0 += GBK) {
        const bool has_next = (k0 + GBK) < K;
        float4 av, bv;
        if (has_next) {
            av = *(const float4*)(A + (size_t)(bm + arow) * K + k0 + GBK + ak);
            bv = *(const float4*)(B + (size_t)(k0 + GBK + brow) * N + bn + bcol);
        }

        const float* Asp = As[p];
        const float* Bsp = Bs[p];
#pragma unroll
        for (int kk = 0; kk < GBK; kk++) {
            float4 a0 = *(const float4*)&Asp[kk * GBM + ty * 4];        // broadcast
            float4 a1 = *(const float4*)&Asp[kk * GBM + 64 + ty * 4];   // broadcast
            ulonglong2 b0 = *(const ulonglong2*)&Bsp[kk * GBN + tx * 4];      // CF
            ulonglong2 b1 = *(const ulonglong2*)&Bsp[kk * GBN + 64 + tx * 4]; // CF
            ull b2[4] = {b0.x, b0.y, b1.x, b1.y};
            ull aa[8] = {pk2(a0.x, a0.x), pk2(a0.y, a0.y), pk2(a0.z, a0.z), pk2(a0.w, a0.w),
                         pk2(a1.x, a1.x), pk2(a1.y, a1.y), pk2(a1.z, a1.z), pk2(a1.w, a1.w)};
#pragma unroll
            for (int i = 0; i < 8; i++)
#pragma unroll
                for (int j = 0; j < 4; j++)
                    acc2[i][j] = fma2(aa[i], b2[j], acc2[i][j]);
        }

        if (has_next) {
            const int q = p ^ 1;
            As[q][(ak + 0) * GBM + arow] = av.x;
            As[q][(ak + 1) * GBM + arow] = av.y;
            As[q][(ak + 2) * GBM + arow] = av.z;
            As[q][(ak + 3) * GBM + arow] = av.w;
            *(float4*)&Bs[q][brow * GBN + bcol] = bv;
            __syncthreads();
            p = q;
        }
    }

#pragma unroll
    for (int i = 0; i < 8; i++) {
        const int row = bm + ((i < 4) ? (ty * 4 + i) : (64 + ty * 4 + i - 4));
        float vlo[4], vhi[4];
        {
            float2 v0 = upk2(acc2[i][0]);
            float2 v1 = upk2(acc2[i][1]);
            vlo[0] = v0.x; vlo[1] = v0.y; vlo[2] = v1.x; vlo[3] = v1.y;
            float2 v2 = upk2(acc2[i][2]);
            float2 v3 = upk2(acc2[i][3]);
            vhi[0] = v2.x; vhi[1] = v2.y; vhi[2] = v3.x; vhi[3] = v3.y;
        }
#pragma unroll
        for (int j = 0; j < 4; j++) {
            const int clo = bn + tx * 4 + j;
            const int chi = bn + 64 + tx * 4 + j;
            float zl = vlo[j], zh = vhi[j];
            if (mode == 1)      { zl *= scale; zh *= scale; }
            else if (mode == 2) {
                zl = 1.f / (1.f + __expf(-(zl + evec[clo])));
                zh = 1.f / (1.f + __expf(-(zh + evec[chi])));
            }
            else if (mode == 3) { zl += evec[clo]; zh += evec[chi]; }
            vlo[j] = zl; vhi[j] = zh;
        }
        *(float4*)(C + (size_t)row * N + bn + tx * 4) =
            make_float4(vlo[0], vlo[1], vlo[2], vlo[3]);
        *(float4*)(C + (size_t)row * N + bn + 64 + tx * 4) =
            make_float4(vhi[0], vhi[1], vhi[2], vhi[3]);
    }
}

// ---------------------------------------------------------------------------
// Attention v5: pass-1 with FUSED in-register softmax (warp-shuffle row
// reductions), storing NORMALIZED P; then one barrier; then pass-2.
// Block = (h, s, qh): 128 q rows x 256 k, 256 threads, 2 barriers total.
// Key invariant: a pass-1 warp's 32 lanes share the same 8 q rows and
// jointly cover all 256 k (lane ki covers {4ki..4ki+3} u {128+4ki..+3}),
// so softmax reductions are shfl.bfly over the warp.
// ---------------------------------------------------------------------------
#define LSTR 268
#define OFF_KS   34304
#define OFF_QS   42496
#define OFF_VS   46592
#define OFF_ADDM 54784
#define ATTN_SMEM_BYTES (55040 * 4)

__global__ __launch_bounds__(256, 1)
void attn5(const float* __restrict__ Q, const float* __restrict__ Km,
           const float* __restrict__ V, const float* __restrict__ G,
           const float* __restrict__ bias, const void* __restrict__ mask,
           float* __restrict__ O)
{
    extern __shared__ float sm[];
    float* L    = sm;                 // holds normalized P after pass 1
    float* Ks   = sm + OFF_KS;
    float* Qs   = sm + OFF_QS;
    float* Vs   = sm + OFF_VS;
    float* addm = sm + OFF_ADDM;

    const int h  = blockIdx.x;
    const int s  = blockIdx.y;
    const int qh = blockIdx.z;
    const int t  = threadIdx.x;

    // ---- stage Q transposed: Qs[c][q] ----
    {
        const int q = t >> 1, c0 = (t & 1) * 16;
        const float4* src = (const float4*)(Q + ((size_t)(s * S_DIM + qh * 128 + q)) * CQK + h * CH + c0);
#pragma unroll
        for (int j = 0; j < 4; j++) {
            float4 v = src[j];
            Qs[(c0 + 4 * j + 0) * 128 + q] = v.x;
            Qs[(c0 + 4 * j + 1) * 128 + q] = v.y;
            Qs[(c0 + 4 * j + 2) * 128 + q] = v.z;
            Qs[(c0 + 4 * j + 3) * 128 + q] = v.w;
        }
    }
    // ---- stage K transposed: Ks[c][k] ----
    {
        const int k = t;
        const float4* src = (const float4*)(Km + ((size_t)(s * S_DIM + k)) * CQK + h * CH);
#pragma unroll
        for (int j = 0; j < 8; j++) {
            float4 v = src[j];
            Ks[(4 * j + 0) * S_DIM + k] = v.x;
            Ks[(4 * j + 1) * S_DIM + k] = v.y;
            Ks[(4 * j + 2) * S_DIM + k] = v.z;
            Ks[(4 * j + 3) * S_DIM + k] = v.w;
        }
    }
    // ---- stage V natural [k][c] + mask ----
    {
        const float4* Vg4 = (const float4*)V;
        const size_t rowbase = ((size_t)s * S_DIM) * (CQK / 4) + h * (CH / 4);
#pragma unroll
        for (int f = t; f < S_DIM * (CH / 4); f += 256) {
            int k = f >> 3, c4 = f & 7;
            ((float4*)Vs)[k * 8 + c4] = Vg4[rowbase + (size_t)k * (CQK / 4) + c4];
        }
        const int idx = s * S_DIM + t;
        const int code = g_mask_code;
        bool mv;
        if (code == 2)      mv = ((const float*)mask)[idx] != 0.f;
        else if (code == 1) mv = ((const unsigned char*)mask)[idx] != 0;
        else                mv = ((const int*)mask)[idx] != 0;
        addm[t] = mv ? 0.f : -1e30f;
    }
    __syncthreads();

    // ---- pass 1 + fused softmax ----
    const float* brow = bias + ((size_t)(h * S_DIM + qh * 128)) * S_DIM;
#pragma unroll
    for (int rep = 0; rep < 2; rep++) {
        const int tile = t + rep * 256;
        const int qi = tile >> 5, ki = tile & 31;   // qi warp-uniform
        const int q0 = qi * 8;
        const int kA = ki * 4, kB = 128 + ki * 4;

        ull acc2[8][4];
#pragma unroll
        for (int i = 0; i < 8; i++)
#pragma unroll
            for (int j = 0; j < 4; j++) acc2[i][j] = 0ULL;

#pragma unroll 2
        for (int c = 0; c < CH; c++) {
            float4 qa = *(const float4*)&Qs[c * 128 + q0];        // broadcast
            float4 qb = *(const float4*)&Qs[c * 128 + q0 + 4];    // broadcast
            ulonglong2 k0v = *(const ulonglong2*)&Ks[c * S_DIM + kA];  // CF
            ulonglong2 k1v = *(const ulonglong2*)&Ks[c * S_DIM + kB];  // CF
            ull b2[4] = {k0v.x, k0v.y, k1v.x, k1v.y};
            ull aa[8] = {pk2(qa.x, qa.x), pk2(qa.y, qa.y), pk2(qa.z, qa.z), pk2(qa.w, qa.w),
                         pk2(qb.x, qb.x), pk2(qb.y, qb.y), pk2(qb.z, qb.z), pk2(qb.w, qb.w)};
#pragma unroll
            for (int i = 0; i < 8; i++)
#pragma unroll
                for (int j = 0; j < 4; j++)
                    acc2[i][j] = fma2(aa[i], b2[j], acc2[i][j]);
        }

        // unpack + bias + mask into v[8][8]
        float v[8][8];
        {
            float4 amA = *(const float4*)&addm[kA];
            float4 amB = *(const float4*)&addm[kB];
#pragma unroll
            for (int i = 0; i < 8; i++) {
                const int q = q0 + i;
                float4 bbA = *(const float4*)(brow + (size_t)q * S_DIM + kA);
                float4 bbB = *(const float4*)(brow + (size_t)q * S_DIM + kB);
                float2 d0 = upk2(acc2[i][0]);
                float2 d1 = upk2(acc2[i][1]);
                float2 d2 = upk2(acc2[i][2]);
                float2 d3 = upk2(acc2[i][3]);
                v[i][0] = d0.x + bbA.x + amA.x;
                v[i][1] = d0.y + bbA.y + amA.y;
                v[i][2] = d1.x + bbA.z + amA.z;
                v[i][3] = d1.y + bbA.w + amA.w;
                v[i][4] = d2.x + bbB.x + amB.x;
                v[i][5] = d2.y + bbB.y + amB.y;
                v[i][6] = d3.x + bbB.z + amB.z;
                v[i][7] = d3.y + bbB.w + amB.w;
            }
        }

        // row max across warp (ILP-8 butterfly)
        float rm[8];
#pragma unroll
        for (int i = 0; i < 8; i++) {
            float m01 = fmaxf(fmaxf(v[i][0], v[i][1]), fmaxf(v[i][2], v[i][3]));
            float m23 = fmaxf(fmaxf(v[i][4], v[i][5]), fmaxf(v[i][6], v[i][7]));
            rm[i] = fmaxf(m01, m23);
        }
#pragma unroll
        for (int st = 16; st >= 1; st >>= 1)
#pragma unroll
            for (int i = 0; i < 8; i++)
                rm[i] = fmaxf(rm[i], __shfl_xor_sync(0xFFFFFFFFu, rm[i], st));

        // exp + row sum across warp
        float rs[8];
#pragma unroll
        for (int i = 0; i < 8; i++) {
            float s0 = 0.f;
#pragma unroll
            for (int j = 0; j < 8; j++) {
                v[i][j] = __expf(v[i][j] - rm[i]);
                s0 += v[i][j];
            }
            rs[i] = s0;
        }
#pragma unroll
        for (int st = 16; st >= 1; st >>= 1)
#pragma unroll
            for (int i = 0; i < 8; i++)
                rs[i] += __shfl_xor_sync(0xFFFFFFFFu, rs[i], st);

        // normalize + store P
#pragma unroll
        for (int i = 0; i < 8; i++) {
            const int q = q0 + i;
            const float riv = 1.f / rs[i];
            *(float4*)&L[q * LSTR + kA] = make_float4(
                v[i][0] * riv, v[i][1] * riv, v[i][2] * riv, v[i][3] * riv);
            *(float4*)&L[q * LSTR + kB] = make_float4(
                v[i][4] * riv, v[i][5] * riv, v[i][6] * riv, v[i][7] * riv);
        }
    }
    __syncthreads();

    // ---- pass 2: O = P.V, 4q x 4c per thread (P pre-normalized) ----
    {
        const int qi = t >> 3, ci = t & 7;
        const int q0 = qi * 4, c0 = ci * 4;
        ull acc2[4][2];
#pragma unroll
        for (int i = 0; i < 4; i++) { acc2[i][0] = 0ULL; acc2[i][1] = 0ULL; }

#pragma unroll 2
        for (int k0 = 0; k0 < S_DIM; k0 += 4) {
            ulonglong2 v0 = *(const ulonglong2*)&Vs[(k0 + 0) * CH + c0];
            ulonglong2 v1 = *(const ulonglong2*)&Vs[(k0 + 1) * CH + c0];
            ulonglong2 v2 = *(const ulonglong2*)&Vs[(k0 + 2) * CH + c0];
            ulonglong2 v3 = *(const ulonglong2*)&Vs[(k0 + 3) * CH + c0];
#pragma unroll
            for (int i = 0; i < 4; i++) {
                float4 pv = *(const float4*)&L[(q0 + i) * LSTR + k0];
                ull a0 = pk2(pv.x, pv.x);
                ull a1 = pk2(pv.y, pv.y);
                ull a2 = pk2(pv.z, pv.z);
                ull a3 = pk2(pv.w, pv.w);
                acc2[i][0] = fma2(a0, v0.x, acc2[i][0]);
                acc2[i][1] = fma2(a0, v0.y, acc2[i][1]);
                acc2[i][0] = fma2(a1, v1.x, acc2[i][0]);
                acc2[i][1] = fma2(a1, v1.y, acc2[i][1]);
                acc2[i][0] = fma2(a2, v2.x, acc2[i][0]);
                acc2[i][1] = fma2(a2, v2.y, acc2[i][1]);
                acc2[i][0] = fma2(a3, v3.x, acc2[i][0]);
                acc2[i][1] = fma2(a3, v3.y, acc2[i][1]);
            }
        }
#pragma unroll
        for (int i = 0; i < 4; i++) {
            const int q = q0 + i;
            const size_t row = (size_t)(s * S_DIM + qh * 128 + q);
            float4 gv = *(const float4*)(G + row * CQK + h * CH + c0);
            float2 x0 = upk2(acc2[i][0]);
            float2 x1 = upk2(acc2[i][1]);
            float4 ov;
            ov.x = x0.x * gv.x;
            ov.y = x0.y * gv.y;
            ov.z = x1.x * gv.z;
            ov.w = x1.y * gv.w;
            *(float4*)(O + row * CQK + h * CH + c0) = ov;
        }
    }
}

// ---------------------------------------------------------------------------
// Launch
// ---------------------------------------------------------------------------
extern "C" void kernel_launch(void* const* d_in, const int* in_sizes, int n_in,
                              void* d_out, int out_size)
{
    const float* x    = (const float*)d_in[0];
    const float* bias = (const float*)d_in[1];
    const void*  mask = d_in[2];
    const float* Wq   = (const float*)d_in[3];
    const float* Wk   = (const float*)d_in[4];
    const float* Wv   = (const float*)d_in[5];
    const float* Wo   = (const float*)d_in[6];
    const float* bo   = (const float*)d_in[7];
    const float* Wg   = (const float*)d_in[8];
    const float* bg   = (const float*)d_in[9];
    float* out = (float*)d_out;

    void *pQ, *pK, *pV, *pG, *pO;
    cudaGetSymbolAddress(&pQ, g_Q);
    cudaGetSymbolAddress(&pK, g_K);
    cudaGetSymbolAddress(&pV, g_V);
    cudaGetSymbolAddress(&pG, g_G);
    cudaGetSymbolAddress(&pO, g_O);
    float* Qb = (float*)pQ; float* Kb = (float*)pK; float* Vb = (float*)pV;
    float* Gb = (float*)pG; float* Ob = (float*)pO;

    const float qscale = 0.17677669529663687f;   // 1/sqrt(32)

    dim3 gproj(CQK / GBN, NROWS / GBM);   // (2, 512)
    sgemm5<<<gproj, 256>>>(x, Wq, Qb, NROWS, CQK, CIN, 1, nullptr, qscale);
    sgemm5<<<gproj, 256>>>(x, Wk, Kb, NROWS, CQK, CIN, 0, nullptr, 1.f);
    sgemm5<<<gproj, 256>>>(x, Wv, Vb, NROWS, CQK, CIN, 0, nullptr, 1.f);
    sgemm5<<<gproj, 256>>>(x, Wg, Gb, NROWS, CQK, CIN, 2, bg, 1.f);

    detect_mask_kernel<<<1, 256>>>((const unsigned char*)mask, S_DIM * S_DIM);

    cudaFuncSetAttribute(attn5, cudaFuncAttributeMaxDynamicSharedMemorySize, ATTN_SMEM_BYTES);
    attn5<<<dim3(NH, S_DIM, 2), 256, ATTN_SMEM_BYTES>>>(Qb, Kb, Vb, Gb, bias, mask, Ob);

    dim3 gout(CIN / GBN, NROWS / GBM);    // (1, 512)
    sgemm5<<<gout, 256>>>(Ob, Wo, out, NROWS, CIN, CQK, 3, bo, 1.f);
}